// round 16
// baseline (speedup 1.0000x reference)
#include <cuda_runtime.h>
#include <cuda_bf16.h>
#include <cstdint>
#include <cstddef>

#define B_ 4096
#define T_ 80
#define V_ 10000
#define E_ 100
#define U_ 1024

#define KTOT 1152            // 1024 (Wh) + 128 (Wx padded from 100)
#define EPAD 128             // padded embedding width
#define NCHUNK 36            // KTOT / 32
#define MT 128
#define NT 128
#define KC 32
#define NSTAGE 3
#define NTHREADS 128
#define LDAB 40              // A row stride in bf16 (80 B): conflict-free ldmatrix

#define ROWB (LDAB * 2)                  // 80 B per row
#define A_PLANE_B (MT * ROWB)            // 10240
#define A_STAGE_B (2 * A_PLANE_B)        // 20480 (hi + lo)
#define SM_A_OFF   0
#define SM_IDX_OFF (NSTAGE * A_STAGE_B)  // 61440
#define SMEM_TOTAL (SM_IDX_OFF + MT * 4) // 61952

#define NBK2 (2 * NCHUNK)                // 72 k16-blocks
#define NSLAB (U_ / 16)                  // 64 n-slabs of 16

// ---- device scratch (allocation-free) ----
__device__ __align__(256) __nv_bfloat16 g_h_hi[2][(size_t)B_ * U_];
__device__ __align__(256) __nv_bfloat16 g_h_lo[2][(size_t)B_ * U_];
__device__ __align__(256) uint4 g_Bfh[(size_t)NBK2 * NSLAB * 32];   // B frags hi
__device__ __align__(256) uint4 g_Bfl[(size_t)NBK2 * NSLAB * 32];   // B frags lo
__device__ __align__(256) __nv_bfloat16 g_emb_hi[(size_t)V_ * EPAD];
__device__ __align__(256) __nv_bfloat16 g_emb_lo[(size_t)V_ * EPAD];

static __device__ __forceinline__ uint32_t smem_u32(const void* p) {
    uint32_t a;
    asm("{ .reg .u64 t; cvta.to.shared.u64 t, %1; cvt.u32.u64 %0, t; }" : "=r"(a) : "l"(p));
    return a;
}
static __device__ __forceinline__ void cp_async16(uint32_t s, const void* g) {
    asm volatile("cp.async.cg.shared.global [%0], [%1], 16;" :: "r"(s), "l"(g));
}
static __device__ __forceinline__ void split_bf16(float v, __nv_bfloat16& hi, __nv_bfloat16& lo) {
    hi = __float2bfloat16(v);
    lo = __float2bfloat16(v - __bfloat162float(hi));
}
static __device__ __forceinline__ void ldsm4(uint32_t* r, uint32_t addr) {
    asm volatile("ldmatrix.sync.aligned.m8n8.x4.shared.b16 {%0,%1,%2,%3}, [%4];"
                 : "=r"(r[0]), "=r"(r[1]), "=r"(r[2]), "=r"(r[3]) : "r"(addr));
}
static __device__ __forceinline__ void mma_bf16(float* c, const uint32_t* a,
                                                uint32_t b0, uint32_t b1) {
    asm volatile("mma.sync.aligned.m16n8k16.row.col.f32.bf16.bf16.f32 "
                 "{%0,%1,%2,%3}, {%4,%5,%6,%7}, {%8,%9}, {%0,%1,%2,%3};"
                 : "+f"(c[0]), "+f"(c[1]), "+f"(c[2]), "+f"(c[3])
                 : "r"(a[0]), "r"(a[1]), "r"(a[2]), "r"(a[3]), "r"(b0), "r"(b1));
}

// ---------------- prep kernels ----------------
// Pre-swizzle B = [Wh^T ; Wx^T ; 0] into exact m16n8k16 B-fragment layout.
__global__ void prep_bf_kernel(const float* __restrict__ Wh, const float* __restrict__ Wx) {
    int idx = blockIdx.x * 256 + threadIdx.x;
    if (idx >= NBK2 * NSLAB * 32) return;
    int lane = idx & 31;
    int nslab = (idx >> 5) & (NSLAB - 1);
    int bk2 = idx >> 11;
    int kbase = (bk2 >> 1) * 32 + (bk2 & 1) * 16;
    uint32_t rh[4], rl[4];
#pragma unroll
    for (int r = 0; r < 4; r++) {
        int n = nslab * 16 + ((r >> 1) & 1) * 8 + (lane >> 2);
        int k = kbase + (r & 1) * 8 + (lane & 3) * 2;
        float v0 = 0.0f, v1 = 0.0f;
        if (k < U_)            v0 = Wh[(size_t)k * U_ + n];
        else if (k < U_ + E_)  v0 = Wx[(size_t)(k - U_) * U_ + n];
        int k1 = k + 1;
        if (k1 < U_)           v1 = Wh[(size_t)k1 * U_ + n];
        else if (k1 < U_ + E_) v1 = Wx[(size_t)(k1 - U_) * U_ + n];
        __nv_bfloat16 h0, l0, h1, l1;
        split_bf16(v0, h0, l0);
        split_bf16(v1, h1, l1);
        __nv_bfloat162 ph = __halves2bfloat162(h0, h1);
        __nv_bfloat162 pl = __halves2bfloat162(l0, l1);
        rh[r] = *(uint32_t*)&ph;
        rl[r] = *(uint32_t*)&pl;
    }
    g_Bfh[idx] = make_uint4(rh[0], rh[1], rh[2], rh[3]);
    g_Bfl[idx] = make_uint4(rl[0], rl[1], rl[2], rl[3]);
}
__global__ void prep_emb_kernel(const float* __restrict__ emb) {
    int idx = blockIdx.x * 256 + threadIdx.x;
    if (idx >= V_ * EPAD) return;
    int tok = idx >> 7;
    int k = idx & (EPAD - 1);
    float v = (k < E_) ? emb[(size_t)tok * E_ + k] : 0.0f;
    __nv_bfloat16 hi, lo; split_bf16(v, hi, lo);
    g_emb_hi[idx] = hi; g_emb_lo[idx] = lo;
}
__global__ void zero_h_kernel() {
    size_t i = (size_t)blockIdx.x * blockDim.x + threadIdx.x;
    if (i < (size_t)B_ * U_) {
        g_h_hi[0][i] = __float2bfloat16(0.0f);
        g_h_lo[0][i] = __float2bfloat16(0.0f);
    }
}

// ---------------- recurrence step ----------------
// Grid (8, 32) = 256 CTAs, 128 threads (4 warps, 2x2 -> 64x64 tiles), 2 CTAs/SM.
// A: cp.async 3-stage SMEM pipeline (one barrier per chunk).
// B: preformatted fragments via LDG.128; single bh/bl buffers with term-phased
//    rotation: hh,lh passes use bh -> prefetch bh(next) -> hl pass uses bl ->
//    prefetch bl(next). Every B load covered by >=32 MMAs. ~215 regs, no spills.
__global__ __launch_bounds__(NTHREADS, 2)
void rnn_step_bf16(const int* __restrict__ inputs, const float* __restrict__ bvec, int t)
{
    extern __shared__ char smem[];
    int* sIdx = (int*)(smem + SM_IDX_OFF);
    const uint32_t sbase = smem_u32(smem);

    const int tid = threadIdx.x;
    const int wid = tid >> 5;
    const int lane = tid & 31;
    const int warp_m = wid & 1;
    const int warp_n = wid >> 1;
    const int n0 = blockIdx.x * NT;
    const int m0 = blockIdx.y * MT;

    const __nv_bfloat16* __restrict__ hh_g = g_h_hi[t & 1];
    const __nv_bfloat16* __restrict__ hl_g = g_h_lo[t & 1];
    __nv_bfloat16* __restrict__ nh = g_h_hi[(t & 1) ^ 1];
    __nv_bfloat16* __restrict__ nl = g_h_lo[(t & 1) ^ 1];

    sIdx[tid] = inputs[(size_t)(m0 + tid) * T_ + t];
    __syncthreads();

    float acc[4][8][4];
#pragma unroll
    for (int i = 0; i < 4; i++)
#pragma unroll
        for (int j = 0; j < 8; j++)
#pragma unroll
            for (int e = 0; e < 4; e++) acc[i][j][e] = 0.0f;

    const int a_r = lane & 15;
    const int a_c = (lane >> 4) * 16;
    const int p_row = tid >> 2, p_sc = tid & 3;

    // A producer (hi+lo planes), 8 cp.async/thread + commit
    auto issue_A = [&](int c) {
        const int s = c % NSTAGE;
        const uint32_t aHiB = sbase + SM_A_OFF + (uint32_t)(s * A_STAGE_B);
        const uint32_t aLoB = aHiB + A_PLANE_B;
        if (c < 32) {
            const __nv_bfloat16* sh = hh_g + (size_t)m0 * U_ + c * KC;
            const __nv_bfloat16* sl = hl_g + (size_t)m0 * U_ + c * KC;
#pragma unroll
            for (int r = 0; r < 4; r++) {
                int row = p_row + r * 32;
                uint32_t off = (uint32_t)(row * ROWB + p_sc * 16);
                cp_async16(aHiB + off, sh + (size_t)row * U_ + p_sc * 8);
                cp_async16(aLoB + off, sl + (size_t)row * U_ + p_sc * 8);
            }
        } else {
            const int kb = (c - 32) * KC;
#pragma unroll
            for (int r = 0; r < 4; r++) {
                int row = p_row + r * 32;
                uint32_t off = (uint32_t)(row * ROWB + p_sc * 16);
                size_t g = (size_t)sIdx[row] * EPAD + kb + p_sc * 8;
                cp_async16(aHiB + off, g_emb_hi + g);
                cp_async16(aLoB + off, g_emb_lo + g);
            }
        }
        asm volatile("cp.async.commit_group;" ::: "memory");
    };

    // B fragment pointers (this CTA+warp's 4 n-slabs)
    const size_t fboff = (size_t)(blockIdx.x * 8 + warp_n * 4) * 32 + lane;
    const uint4* __restrict__ Bfh = g_Bfh + fboff;
    const uint4* __restrict__ Bfl = g_Bfl + fboff;

    uint32_t bh[4][4], bl[4][4];
    auto loadBp = [&](uint32_t (&bb)[4][4], const uint4* __restrict__ Bf, int bk2) {
        size_t base = (size_t)bk2 * (NSLAB * 32);
#pragma unroll
        for (int jj = 0; jj < 4; jj++) {
            uint4 v = __ldg(Bf + base + jj * 32);
            bb[jj][0] = v.x; bb[jj][1] = v.y; bb[jj][2] = v.z; bb[jj][3] = v.w;
        }
    };

    issue_A(0); issue_A(1);
    loadBp(bh, Bfh, 0);
    loadBp(bl, Bfl, 0);

    for (int c = 0; c < NCHUNK; c++) {
        if (c < NCHUNK - 1) asm volatile("cp.async.wait_group 1;" ::: "memory");
        else                asm volatile("cp.async.wait_group 0;" ::: "memory");
        __syncthreads();   // stage (c-1)%3 free, stage c%3 visible
        if (c + 2 < NCHUNK) issue_A(c + 2);

        const uint32_t aBase = sbase + (uint32_t)((c % NSTAGE) * A_STAGE_B)
                             + (uint32_t)(warp_m * 64 * ROWB);

#pragma unroll
        for (int k16 = 0; k16 < 2; k16++) {
            const int bk2 = 2 * c + k16;
            int nbk2 = bk2 + 1; if (nbk2 > NBK2 - 1) nbk2 = NBK2 - 1;

            // A fragments for this k16 (held across all 3 passes)
            uint32_t ah[4][4], al[4][4];
#pragma unroll
            for (int i = 0; i < 4; i++) {
                uint32_t addr = aBase + (uint32_t)((i * 16 + a_r) * ROWB + k16 * 32 + a_c);
                ldsm4(ah[i], addr);
                ldsm4(al[i], addr + A_PLANE_B);
            }
            // Pass 1: hi(A) x hi(B)
#pragma unroll
            for (int i = 0; i < 4; i++)
#pragma unroll
                for (int jj = 0; jj < 4; jj++) {
                    mma_bf16(acc[i][2 * jj],     ah[i], bh[jj][0], bh[jj][1]);
                    mma_bf16(acc[i][2 * jj + 1], ah[i], bh[jj][2], bh[jj][3]);
                }
            // Pass 2: lo(A) x hi(B)
#pragma unroll
            for (int i = 0; i < 4; i++)
#pragma unroll
                for (int jj = 0; jj < 4; jj++) {
                    mma_bf16(acc[i][2 * jj],     al[i], bh[jj][0], bh[jj][1]);
                    mma_bf16(acc[i][2 * jj + 1], al[i], bh[jj][2], bh[jj][3]);
                }
            // bh dead -> prefetch next block's hi plane (covered by hl pass)
            loadBp(bh, Bfh, nbk2);
            // Pass 3: hi(A) x lo(B)
#pragma unroll
            for (int i = 0; i < 4; i++)
#pragma unroll
                for (int jj = 0; jj < 4; jj++) {
                    mma_bf16(acc[i][2 * jj],     ah[i], bl[jj][0], bl[jj][1]);
                    mma_bf16(acc[i][2 * jj + 1], ah[i], bl[jj][2], bl[jj][3]);
                }
            // bl dead -> prefetch next block's lo plane (covered by next hh+lh)
            loadBp(bl, Bfl, nbk2);
        }
    }

    // ---- epilogue: bias + tanh + bf16 hi/lo split + direct store ----
    const int er = lane >> 2;
    const int ec = (lane & 3) * 2;
#pragma unroll
    for (int j = 0; j < 8; j++) {
        int gc = n0 + warp_n * 64 + j * 8 + ec;
        float bia0 = bvec[gc], bia1 = bvec[gc + 1];
#pragma unroll
        for (int i = 0; i < 4; i++) {
            int gr = m0 + warp_m * 64 + i * 16 + er;
            float t0 = tanhf(acc[i][j][0] + bia0);
            float t1 = tanhf(acc[i][j][1] + bia1);
            float t2 = tanhf(acc[i][j][2] + bia0);
            float t3 = tanhf(acc[i][j][3] + bia1);
            __nv_bfloat16 h0, l0, h1, l1;
            split_bf16(t0, h0, l0); split_bf16(t1, h1, l1);
            size_t o0 = (size_t)gr * U_ + gc;
            *(__nv_bfloat162*)(nh + o0) = __halves2bfloat162(h0, h1);
            *(__nv_bfloat162*)(nl + o0) = __halves2bfloat162(l0, l1);
            split_bf16(t2, h0, l0); split_bf16(t3, h1, l1);
            size_t o1 = (size_t)(gr + 8) * U_ + gc;
            *(__nv_bfloat162*)(nh + o1) = __halves2bfloat162(h0, h1);
            *(__nv_bfloat162*)(nl + o1) = __halves2bfloat162(l0, l1);
        }
    }
}

// out[row] = h_last[row, :] @ Wo + bo
__global__ void final_proj_kernel(const float* __restrict__ Wo,
                                  const float* __restrict__ bo,
                                  float* __restrict__ out)
{
    const __nv_bfloat16* hh = g_h_hi[0];   // T_=80 even -> final state in buffer 0
    const __nv_bfloat16* hl = g_h_lo[0];
    int row = blockIdx.x;
    int tid = threadIdx.x;     // 128 threads
    float s = 0.0f;
    size_t base = (size_t)row * U_;
#pragma unroll 4
    for (int i = tid; i < U_; i += 128) {
        float hv = __bfloat162float(hh[base + i]) + __bfloat162float(hl[base + i]);
        s += hv * Wo[i];
    }
#pragma unroll
    for (int o = 16; o > 0; o >>= 1) s += __shfl_down_sync(0xffffffffu, s, o);
    __shared__ float red[4];
    if ((tid & 31) == 0) red[tid >> 5] = s;
    __syncthreads();
    if (tid == 0) out[row] = red[0] + red[1] + red[2] + red[3] + bo[0];
}

extern "C" void kernel_launch(void* const* d_in, const int* in_sizes, int n_in,
                              void* d_out, int out_size)
{
    const int*   inputs = (const int*)  d_in[0];
    const float* emb    = (const float*)d_in[1];
    const float* Wx     = (const float*)d_in[2];
    const float* Wh     = (const float*)d_in[3];
    const float* b      = (const float*)d_in[4];
    const float* Wo     = (const float*)d_in[5];
    const float* bo     = (const float*)d_in[6];
    float* out = (float*)d_out;

    cudaFuncSetAttribute(rnn_step_bf16, cudaFuncAttributeMaxDynamicSharedMemorySize,
                         SMEM_TOTAL);

    // Prep: fragment-form bf16 weights, split embedding, h0 = 0
    prep_bf_kernel<<<(NBK2 * NSLAB * 32 + 255) / 256, 256>>>(Wh, Wx);
    prep_emb_kernel<<<(V_ * EPAD + 255) / 256, 256>>>(emb);
    {
        size_t n = (size_t)B_ * U_;
        zero_h_kernel<<<(int)((n + 255) / 256), 256>>>();
    }

    // 80 recurrence steps (ping-pong hi/lo planes)
    dim3 grid(U_ / NT, B_ / MT);
    for (int t = 0; t < T_; t++) {
        rnn_step_bf16<<<grid, NTHREADS, SMEM_TOTAL>>>(inputs, b, t);
    }

    final_proj_kernel<<<B_, 128>>>(Wo, bo, out);
}

// round 17
// speedup vs baseline: 1.1208x; 1.1208x over previous
#include <cuda_runtime.h>
#include <cuda_bf16.h>
#include <cstdint>
#include <cstddef>

#define B_ 4096
#define T_ 80
#define V_ 10000
#define E_ 100
#define U_ 1024

#define KTOT 1152            // 1024 (Wh) + 128 (Wx padded from 100)
#define EPAD 128             // padded embedding width
#define NCHUNK 36            // KTOT / 32
#define MT 128
#define NT 128
#define KC 32
#define NSTAGE 3
#define NTHREADS 128
#define LDAB 40              // A row stride in bf16 (80 B): conflict-free ldmatrix

#define ROWB (LDAB * 2)                  // 80 B per row
#define A_PLANE_B (MT * ROWB)            // 10240
#define A_STAGE_B (2 * A_PLANE_B)        // 20480 (hi + lo)
#define SM_A_OFF   0
#define SM_IDX_OFF (NSTAGE * A_STAGE_B)  // 61440
#define SMEM_TOTAL (SM_IDX_OFF + MT * 4) // 61952

#define NBK2 (2 * NCHUNK)                // 72 k16-blocks
#define NSLAB (U_ / 16)                  // 64 n-slabs of 16

#define MG_HALF 16                       // m-groups per chain (32 total)

// ---- device scratch (allocation-free) ----
__device__ __align__(256) __nv_bfloat16 g_h_hi[2][(size_t)B_ * U_];
__device__ __align__(256) __nv_bfloat16 g_h_lo[2][(size_t)B_ * U_];
__device__ __align__(256) uint4 g_Bfh[(size_t)NBK2 * NSLAB * 32];   // B frags hi
__device__ __align__(256) uint4 g_Bfl[(size_t)NBK2 * NSLAB * 32];   // B frags lo
__device__ __align__(256) __nv_bfloat16 g_emb_hi[(size_t)V_ * EPAD];
__device__ __align__(256) __nv_bfloat16 g_emb_lo[(size_t)V_ * EPAD];

static __device__ __forceinline__ uint32_t smem_u32(const void* p) {
    uint32_t a;
    asm("{ .reg .u64 t; cvta.to.shared.u64 t, %1; cvt.u32.u64 %0, t; }" : "=r"(a) : "l"(p));
    return a;
}
static __device__ __forceinline__ void cp_async16(uint32_t s, const void* g) {
    asm volatile("cp.async.cg.shared.global [%0], [%1], 16;" :: "r"(s), "l"(g));
}
static __device__ __forceinline__ void split_bf16(float v, __nv_bfloat16& hi, __nv_bfloat16& lo) {
    hi = __float2bfloat16(v);
    lo = __float2bfloat16(v - __bfloat162float(hi));
}
static __device__ __forceinline__ void ldsm4(uint32_t* r, uint32_t addr) {
    asm volatile("ldmatrix.sync.aligned.m8n8.x4.shared.b16 {%0,%1,%2,%3}, [%4];"
                 : "=r"(r[0]), "=r"(r[1]), "=r"(r[2]), "=r"(r[3]) : "r"(addr));
}
static __device__ __forceinline__ void mma_bf16(float* c, const uint32_t* a,
                                                uint32_t b0, uint32_t b1) {
    asm volatile("mma.sync.aligned.m16n8k16.row.col.f32.bf16.bf16.f32 "
                 "{%0,%1,%2,%3}, {%4,%5,%6,%7}, {%8,%9}, {%0,%1,%2,%3};"
                 : "+f"(c[0]), "+f"(c[1]), "+f"(c[2]), "+f"(c[3])
                 : "r"(a[0]), "r"(a[1]), "r"(a[2]), "r"(a[3]), "r"(b0), "r"(b1));
}

// ---------------- prep kernels ----------------
__global__ void prep_bf_kernel(const float* __restrict__ Wh, const float* __restrict__ Wx) {
    int idx = blockIdx.x * 256 + threadIdx.x;
    if (idx >= NBK2 * NSLAB * 32) return;
    int lane = idx & 31;
    int nslab = (idx >> 5) & (NSLAB - 1);
    int bk2 = idx >> 11;
    int kbase = (bk2 >> 1) * 32 + (bk2 & 1) * 16;
    uint32_t rh[4], rl[4];
#pragma unroll
    for (int r = 0; r < 4; r++) {
        int n = nslab * 16 + ((r >> 1) & 1) * 8 + (lane >> 2);
        int k = kbase + (r & 1) * 8 + (lane & 3) * 2;
        float v0 = 0.0f, v1 = 0.0f;
        if (k < U_)            v0 = Wh[(size_t)k * U_ + n];
        else if (k < U_ + E_)  v0 = Wx[(size_t)(k - U_) * U_ + n];
        int k1 = k + 1;
        if (k1 < U_)           v1 = Wh[(size_t)k1 * U_ + n];
        else if (k1 < U_ + E_) v1 = Wx[(size_t)(k1 - U_) * U_ + n];
        __nv_bfloat16 h0, l0, h1, l1;
        split_bf16(v0, h0, l0);
        split_bf16(v1, h1, l1);
        __nv_bfloat162 ph = __halves2bfloat162(h0, h1);
        __nv_bfloat162 pl = __halves2bfloat162(l0, l1);
        rh[r] = *(uint32_t*)&ph;
        rl[r] = *(uint32_t*)&pl;
    }
    g_Bfh[idx] = make_uint4(rh[0], rh[1], rh[2], rh[3]);
    g_Bfl[idx] = make_uint4(rl[0], rl[1], rl[2], rl[3]);
}
__global__ void prep_emb_kernel(const float* __restrict__ emb) {
    int idx = blockIdx.x * 256 + threadIdx.x;
    if (idx >= V_ * EPAD) return;
    int tok = idx >> 7;
    int k = idx & (EPAD - 1);
    float v = (k < E_) ? emb[(size_t)tok * E_ + k] : 0.0f;
    __nv_bfloat16 hi, lo; split_bf16(v, hi, lo);
    g_emb_hi[idx] = hi; g_emb_lo[idx] = lo;
}
__global__ void zero_h_kernel() {
    size_t i = (size_t)blockIdx.x * blockDim.x + threadIdx.x;
    if (i < (size_t)B_ * U_) {
        g_h_hi[0][i] = __float2bfloat16(0.0f);
        g_h_lo[0][i] = __float2bfloat16(0.0f);
    }
}

// ---------------- recurrence step (R14 mainloop, m-offset for chain split) ----------
// Grid (8, 16) = 128 CTAs per chain kernel, 128 threads (4 warps, 2x2 -> 64x64).
// A: cp.async 3-stage SMEM pipeline (one barrier per chunk).
// B: preformatted fragments via LDG.128 from L2, register double-buffered (X/Y).
__global__ __launch_bounds__(NTHREADS, 2)
void rnn_step_bf16(const int* __restrict__ inputs, const float* __restrict__ bvec,
                   int t, int mg0)
{
    extern __shared__ char smem[];
    int* sIdx = (int*)(smem + SM_IDX_OFF);
    const uint32_t sbase = smem_u32(smem);

    const int tid = threadIdx.x;
    const int wid = tid >> 5;
    const int lane = tid & 31;
    const int warp_m = wid & 1;
    const int warp_n = wid >> 1;
    const int n0 = blockIdx.x * NT;
    const int m0 = (mg0 + blockIdx.y) * MT;

    const __nv_bfloat16* __restrict__ hh_g = g_h_hi[t & 1];
    const __nv_bfloat16* __restrict__ hl_g = g_h_lo[t & 1];
    __nv_bfloat16* __restrict__ nh = g_h_hi[(t & 1) ^ 1];
    __nv_bfloat16* __restrict__ nl = g_h_lo[(t & 1) ^ 1];

    sIdx[tid] = inputs[(size_t)(m0 + tid) * T_ + t];
    __syncthreads();

    float acc[4][8][4];
#pragma unroll
    for (int i = 0; i < 4; i++)
#pragma unroll
        for (int j = 0; j < 8; j++)
#pragma unroll
            for (int e = 0; e < 4; e++) acc[i][j][e] = 0.0f;

    const int a_r = lane & 15;
    const int a_c = (lane >> 4) * 16;
    const int p_row = tid >> 2, p_sc = tid & 3;

    auto issue_A = [&](int c) {
        const int s = c % NSTAGE;
        const uint32_t aHiB = sbase + SM_A_OFF + (uint32_t)(s * A_STAGE_B);
        const uint32_t aLoB = aHiB + A_PLANE_B;
        if (c < 32) {
            const __nv_bfloat16* sh = hh_g + (size_t)m0 * U_ + c * KC;
            const __nv_bfloat16* sl = hl_g + (size_t)m0 * U_ + c * KC;
#pragma unroll
            for (int r = 0; r < 4; r++) {
                int row = p_row + r * 32;
                uint32_t off = (uint32_t)(row * ROWB + p_sc * 16);
                cp_async16(aHiB + off, sh + (size_t)row * U_ + p_sc * 8);
                cp_async16(aLoB + off, sl + (size_t)row * U_ + p_sc * 8);
            }
        } else {
            const int kb = (c - 32) * KC;
#pragma unroll
            for (int r = 0; r < 4; r++) {
                int row = p_row + r * 32;
                uint32_t off = (uint32_t)(row * ROWB + p_sc * 16);
                size_t g = (size_t)sIdx[row] * EPAD + kb + p_sc * 8;
                cp_async16(aHiB + off, g_emb_hi + g);
                cp_async16(aLoB + off, g_emb_lo + g);
            }
        }
        asm volatile("cp.async.commit_group;" ::: "memory");
    };

    const size_t fboff = (size_t)(blockIdx.x * 8 + warp_n * 4) * 32 + lane;
    const uint4* __restrict__ Bfh = g_Bfh + fboff;
    const uint4* __restrict__ Bfl = g_Bfl + fboff;

    uint32_t Xh[4][4], Xl[4][4], Yh[4][4], Yl[4][4];
    auto loadB = [&](uint32_t (&bh)[4][4], uint32_t (&bl)[4][4], int bk2) {
        size_t base = (size_t)bk2 * (NSLAB * 32);
#pragma unroll
        for (int jj = 0; jj < 4; jj++) {
            uint4 vh = __ldg(Bfh + base + jj * 32);
            uint4 vl = __ldg(Bfl + base + jj * 32);
            bh[jj][0] = vh.x; bh[jj][1] = vh.y; bh[jj][2] = vh.z; bh[jj][3] = vh.w;
            bl[jj][0] = vl.x; bl[jj][1] = vl.y; bl[jj][2] = vl.z; bl[jj][3] = vl.w;
        }
    };

    auto computeK16 = [&](uint32_t aBase, int k16,
                          uint32_t (&bh)[4][4], uint32_t (&bl)[4][4]) {
        uint32_t ah[2][4], al[2][4];
        {
            uint32_t addr = aBase + (uint32_t)(a_r * ROWB + k16 * 32 + a_c);
            ldsm4(ah[0], addr);
            ldsm4(al[0], addr + A_PLANE_B);
        }
#pragma unroll
        for (int i = 0; i < 4; i++) {
            const int cur = i & 1;
            if (i < 3) {
                uint32_t addr = aBase + (uint32_t)(((i + 1) * 16 + a_r) * ROWB + k16 * 32 + a_c);
                ldsm4(ah[cur ^ 1], addr);
                ldsm4(al[cur ^ 1], addr + A_PLANE_B);
            }
#pragma unroll
            for (int jj = 0; jj < 4; jj++) {
                mma_bf16(acc[i][2 * jj],     ah[cur], bh[jj][0], bh[jj][1]);
                mma_bf16(acc[i][2 * jj],     al[cur], bh[jj][0], bh[jj][1]);
                mma_bf16(acc[i][2 * jj],     ah[cur], bl[jj][0], bl[jj][1]);
                mma_bf16(acc[i][2 * jj + 1], ah[cur], bh[jj][2], bh[jj][3]);
                mma_bf16(acc[i][2 * jj + 1], al[cur], bh[jj][2], bh[jj][3]);
                mma_bf16(acc[i][2 * jj + 1], ah[cur], bl[jj][2], bl[jj][3]);
            }
        }
    };

    issue_A(0); issue_A(1);
    loadB(Xh, Xl, 0);

    for (int c = 0; c < NCHUNK; c++) {
        if (c < NCHUNK - 1) asm volatile("cp.async.wait_group 1;" ::: "memory");
        else                asm volatile("cp.async.wait_group 0;" ::: "memory");
        __syncthreads();   // single barrier: stage (c-1)%3 free, stage c%3 visible
        if (c + 2 < NCHUNK) issue_A(c + 2);

        const uint32_t aBase = sbase + (uint32_t)((c % NSTAGE) * A_STAGE_B)
                             + (uint32_t)(warp_m * 64 * ROWB);

        loadB(Yh, Yl, 2 * c + 1);
        computeK16(aBase, 0, Xh, Xl);
        int nbk2 = 2 * c + 2; if (nbk2 > NBK2 - 1) nbk2 = NBK2 - 1;
        loadB(Xh, Xl, nbk2);
        computeK16(aBase, 1, Yh, Yl);
    }

    // ---- epilogue: bias + tanh + bf16 hi/lo split + direct store ----
    const int er = lane >> 2;
    const int ec = (lane & 3) * 2;
#pragma unroll
    for (int j = 0; j < 8; j++) {
        int gc = n0 + warp_n * 64 + j * 8 + ec;
        float bia0 = bvec[gc], bia1 = bvec[gc + 1];
#pragma unroll
        for (int i = 0; i < 4; i++) {
            int gr = m0 + warp_m * 64 + i * 16 + er;
            float t0 = tanhf(acc[i][j][0] + bia0);
            float t1 = tanhf(acc[i][j][1] + bia1);
            float t2 = tanhf(acc[i][j][2] + bia0);
            float t3 = tanhf(acc[i][j][3] + bia1);
            __nv_bfloat16 h0, l0, h1, l1;
            split_bf16(t0, h0, l0); split_bf16(t1, h1, l1);
            size_t o0 = (size_t)gr * U_ + gc;
            *(__nv_bfloat162*)(nh + o0) = __halves2bfloat162(h0, h1);
            *(__nv_bfloat162*)(nl + o0) = __halves2bfloat162(l0, l1);
            split_bf16(t2, h0, l0); split_bf16(t3, h1, l1);
            size_t o1 = (size_t)(gr + 8) * U_ + gc;
            *(__nv_bfloat162*)(nh + o1) = __halves2bfloat162(h0, h1);
            *(__nv_bfloat162*)(nl + o1) = __halves2bfloat162(l0, l1);
        }
    }
}

// out[row] = h_last[row, :] @ Wo + bo
__global__ void final_proj_kernel(const float* __restrict__ Wo,
                                  const float* __restrict__ bo,
                                  float* __restrict__ out)
{
    const __nv_bfloat16* hh = g_h_hi[0];   // T_=80 even -> final state in buffer 0
    const __nv_bfloat16* hl = g_h_lo[0];
    int row = blockIdx.x;
    int tid = threadIdx.x;     // 128 threads
    float s = 0.0f;
    size_t base = (size_t)row * U_;
#pragma unroll 4
    for (int i = tid; i < U_; i += 128) {
        float hv = __bfloat162float(hh[base + i]) + __bfloat162float(hl[base + i]);
        s += hv * Wo[i];
    }
#pragma unroll
    for (int o = 16; o > 0; o >>= 1) s += __shfl_down_sync(0xffffffffu, s, o);
    __shared__ float red[4];
    if ((tid & 31) == 0) red[tid >> 5] = s;
    __syncthreads();
    if (tid == 0) out[row] = red[0] + red[1] + red[2] + red[3] + bo[0];
}

extern "C" void kernel_launch(void* const* d_in, const int* in_sizes, int n_in,
                              void* d_out, int out_size)
{
    const int*   inputs = (const int*)  d_in[0];
    const float* emb    = (const float*)d_in[1];
    const float* Wx     = (const float*)d_in[2];
    const float* Wh     = (const float*)d_in[3];
    const float* b      = (const float*)d_in[4];
    const float* Wo     = (const float*)d_in[5];
    const float* bo     = (const float*)d_in[6];
    float* out = (float*)d_out;

    // One-time host-object setup (streams/events are not device memory).
    static cudaStream_t sA = nullptr, sB = nullptr;
    static cudaEvent_t eFork = nullptr, eA = nullptr, eB = nullptr;
    if (!sA) {
        cudaStreamCreateWithFlags(&sA, cudaStreamNonBlocking);
        cudaStreamCreateWithFlags(&sB, cudaStreamNonBlocking);
        cudaEventCreateWithFlags(&eFork, cudaEventDisableTiming);
        cudaEventCreateWithFlags(&eA, cudaEventDisableTiming);
        cudaEventCreateWithFlags(&eB, cudaEventDisableTiming);
        cudaFuncSetAttribute(rnn_step_bf16, cudaFuncAttributeMaxDynamicSharedMemorySize,
                             SMEM_TOTAL);
    }

    // Prep: fragment-form bf16 weights, split embedding, h0 = 0 (default stream)
    prep_bf_kernel<<<(NBK2 * NSLAB * 32 + 255) / 256, 256>>>(Wh, Wx);
    prep_emb_kernel<<<(V_ * EPAD + 255) / 256, 256>>>(emb);
    {
        size_t n = (size_t)B_ * U_;
        zero_h_kernel<<<(int)((n + 255) / 256), 256>>>();
    }

    // Fork: two independent 80-step chains over disjoint batch halves.
    cudaEventRecord(eFork, 0);
    cudaStreamWaitEvent(sA, eFork, 0);
    cudaStreamWaitEvent(sB, eFork, 0);

    dim3 grid(U_ / NT, MG_HALF);
    for (int t = 0; t < T_; t++) {
        rnn_step_bf16<<<grid, NTHREADS, SMEM_TOTAL, sA>>>(inputs, b, t, 0);
        rnn_step_bf16<<<grid, NTHREADS, SMEM_TOTAL, sB>>>(inputs, b, t, MG_HALF);
    }

    // Join, then final projection on the default stream.
    cudaEventRecord(eA, sA);
    cudaEventRecord(eB, sB);
    cudaStreamWaitEvent(0, eA, 0);
    cudaStreamWaitEvent(0, eB, 0);
    final_proj_kernel<<<B_, 128>>>(Wo, bo, out);
}